// round 4
// baseline (speedup 1.0000x reference)
#include <cuda_runtime.h>
#include <cstddef>

#define D   512
#define Tt  4096
#define BS  8
#define CH  64      // chunk length
#define NCH 64      // number of chunks  (T / CH)
// scan GEMM column count = BS * NCH = 512

// ---------------- device scratch (no allocations allowed) ----------------
__device__ float g_P0[D * D];   // squaring ping
__device__ float g_P1[D * D];   // squaring pong; ends holding A^64
__device__ float g_Q0[D * D];   // fixup P ping (starts holding carries)
__device__ float g_Q1[D * D];   // fixup P pong

__device__ __forceinline__ float* gsel(int s, const float* a) {
    switch (s) {
        case 0:  return (float*)a;
        case 1:  return g_P0;
        case 2:  return g_P1;
        case 3:  return g_Q0;
        default: return g_Q1;
    }
}

// ---------------- K1: Bx = x @ B^T  (written into d_out) ----------------
// out[m, e] = sum_d x[m, d] * B[e, d];  m = b*T + t  (32768 rows)
__global__ __launch_bounds__(256) void bx_gemm(const float* __restrict__ x,
                                               const float* __restrict__ Bm,
                                               float* __restrict__ out) {
    __shared__ float Xs[16][68];
    __shared__ float Bs[16][68];
    const int m0 = blockIdx.y * 64;
    const int n0 = blockIdx.x * 64;
    const int tid = threadIdx.x;
    const int tx = tid & 15, ty = tid >> 4;
    const int lr = tid >> 2;          // 0..63
    const int lk = (tid & 3) * 4;     // 0,4,8,12

    float acc[4][4] = {};

    for (int d0 = 0; d0 < D; d0 += 16) {
        float4 xv = *(const float4*)(x  + (size_t)(m0 + lr) * D + d0 + lk);
        float4 bv = *(const float4*)(Bm + (size_t)(n0 + lr) * D + d0 + lk);
        Xs[lk + 0][lr] = xv.x; Xs[lk + 1][lr] = xv.y;
        Xs[lk + 2][lr] = xv.z; Xs[lk + 3][lr] = xv.w;
        Bs[lk + 0][lr] = bv.x; Bs[lk + 1][lr] = bv.y;
        Bs[lk + 2][lr] = bv.z; Bs[lk + 3][lr] = bv.w;
        __syncthreads();
#pragma unroll
        for (int k = 0; k < 16; k++) {
            float4 a = *(const float4*)&Xs[k][ty * 4];
            float4 b = *(const float4*)&Bs[k][tx * 4];
            acc[0][0] += a.x * b.x; acc[0][1] += a.x * b.y; acc[0][2] += a.x * b.z; acc[0][3] += a.x * b.w;
            acc[1][0] += a.y * b.x; acc[1][1] += a.y * b.y; acc[1][2] += a.y * b.z; acc[1][3] += a.y * b.w;
            acc[2][0] += a.z * b.x; acc[2][1] += a.z * b.y; acc[2][2] += a.z * b.z; acc[2][3] += a.z * b.w;
            acc[3][0] += a.w * b.x; acc[3][1] += a.w * b.y; acc[3][2] += a.w * b.z; acc[3][3] += a.w * b.w;
        }
        __syncthreads();
    }
#pragma unroll
    for (int q = 0; q < 4; q++) {
        float4 r = make_float4(acc[q][0], acc[q][1], acc[q][2], acc[q][3]);
        *(float4*)(out + (size_t)(m0 + ty * 4 + q) * D + n0 + tx * 4) = r;
    }
}

// ---------------- K2: Z = M @ M (512^3 squaring) ----------------
__global__ __launch_bounds__(256) void matmul_sq(const float* __restrict__ Ain,
                                                 int src_sel, int dst_sel) {
    const float* M = gsel(src_sel, Ain);
    float* Z = gsel(dst_sel, nullptr);
    __shared__ float As[16][68];
    __shared__ float Bs[16][64];
    const int c0 = blockIdx.x * 64;
    const int e0 = blockIdx.y * 64;
    const int tid = threadIdx.x;
    const int tx = tid & 15, ty = tid >> 4;
    const int lr = tid >> 2, lk = (tid & 3) * 4;   // A transposed load
    const int bk = tid >> 4, bc = (tid & 15) * 4;  // B direct load

    float acc[4][4] = {};

    for (int d0 = 0; d0 < D; d0 += 16) {
        float4 av = *(const float4*)(M + (size_t)(e0 + lr) * D + d0 + lk);
        As[lk + 0][lr] = av.x; As[lk + 1][lr] = av.y;
        As[lk + 2][lr] = av.z; As[lk + 3][lr] = av.w;
        float4 bv = *(const float4*)(M + (size_t)(d0 + bk) * D + c0 + bc);
        *(float4*)&Bs[bk][bc] = bv;
        __syncthreads();
#pragma unroll
        for (int k = 0; k < 16; k++) {
            float4 a = *(const float4*)&As[k][ty * 4];
            float4 b = *(const float4*)&Bs[k][tx * 4];
            acc[0][0] += a.x * b.x; acc[0][1] += a.x * b.y; acc[0][2] += a.x * b.z; acc[0][3] += a.x * b.w;
            acc[1][0] += a.y * b.x; acc[1][1] += a.y * b.y; acc[1][2] += a.y * b.z; acc[1][3] += a.y * b.w;
            acc[2][0] += a.z * b.x; acc[2][1] += a.z * b.y; acc[2][2] += a.z * b.z; acc[2][3] += a.z * b.w;
            acc[3][0] += a.w * b.x; acc[3][1] += a.w * b.y; acc[3][2] += a.w * b.z; acc[3][3] += a.w * b.w;
        }
        __syncthreads();
    }
#pragma unroll
    for (int q = 0; q < 4; q++) {
        float4 r = make_float4(acc[q][0], acc[q][1], acc[q][2], acc[q][3]);
        *(float4*)(Z + (size_t)(e0 + ty * 4 + q) * D + c0 + tx * 4) = r;
    }
}

// ---------------- K3/K5: one scan step over 512 columns ----------------
// mode 0 (local scan):  out[., t=jC+i] = A @ out[., t-1] + out[., t]
// mode 1 (fixup):       Qdst = A @ Qsrc;  out[., t=jC+i] += Qdst
__global__ __launch_bounds__(256) void scan_step(const float* __restrict__ A,
                                                 float* __restrict__ out,
                                                 int i, int mode,
                                                 int qsrc_sel, int qdst_sel) {
    __shared__ float As[16][68];
    __shared__ float Xs[16][40];
    const int c0 = blockIdx.x * 32;
    const int e0 = blockIdx.y * 64;
    const int tid = threadIdx.x;
    const int tx = tid & 15, ty = tid >> 4;
    const float* Qsrc = gsel(qsrc_sel, nullptr);
    float* Qdst = gsel(qdst_sel, nullptr);

    float acc[4][2] = {};

    const int lr = tid >> 2, lk = (tid & 3) * 4;   // A transposed load
    const float* xcol = nullptr;
    int c_l = 0, lkx = 0;
    if (tid < 128) {
        c_l = tid >> 2;            // 0..31
        lkx = (tid & 3) * 4;
        int cg = c0 + c_l;
        if (mode == 0) {
            int b = cg >> 6, j = cg & 63;
            xcol = out + ((size_t)b * Tt + (size_t)j * CH + (i - 1)) * D;
        } else {
            xcol = Qsrc + (size_t)cg * D;
        }
    }

    for (int d0 = 0; d0 < D; d0 += 16) {
        float4 av = *(const float4*)(A + (size_t)(e0 + lr) * D + d0 + lk);
        As[lk + 0][lr] = av.x; As[lk + 1][lr] = av.y;
        As[lk + 2][lr] = av.z; As[lk + 3][lr] = av.w;
        if (tid < 128) {
            float4 xv = *(const float4*)(xcol + d0 + lkx);
            Xs[lkx + 0][c_l] = xv.x; Xs[lkx + 1][c_l] = xv.y;
            Xs[lkx + 2][c_l] = xv.z; Xs[lkx + 3][c_l] = xv.w;
        }
        __syncthreads();
#pragma unroll
        for (int k = 0; k < 16; k++) {
            float4 a  = *(const float4*)&As[k][ty * 4];
            float2 xv = *(const float2*)&Xs[k][tx * 2];
            acc[0][0] += a.x * xv.x; acc[1][0] += a.y * xv.x;
            acc[2][0] += a.z * xv.x; acc[3][0] += a.w * xv.x;
            acc[0][1] += a.x * xv.y; acc[1][1] += a.y * xv.y;
            acc[2][1] += a.z * xv.y; acc[3][1] += a.w * xv.y;
        }
        __syncthreads();
    }

#pragma unroll
    for (int cj = 0; cj < 2; cj++) {
        int cg = c0 + tx * 2 + cj;
        int b = cg >> 6, j = cg & 63;
        float* optr = out + ((size_t)b * Tt + (size_t)j * CH + i) * D + e0 + ty * 4;
        float4 r = make_float4(acc[0][cj], acc[1][cj], acc[2][cj], acc[3][cj]);
        if (mode == 1) {
            *(float4*)(Qdst + (size_t)cg * D + e0 + ty * 4) = r;
        }
        float4 u = *(const float4*)optr;
        u.x += r.x; u.y += r.y; u.z += r.z; u.w += r.w;
        *(float4*)optr = u;
    }
}

// ---------------- K4a: carries[.,0] = h0 ----------------
__global__ void init_carry(const float* __restrict__ h0) {
    int b = blockIdx.x;     // 8
    int d = threadIdx.x;    // 512
    g_Q0[((size_t)b * NCH + 0) * D + d] = h0[(size_t)b * D + d];
}

// ---------------- K4b: one boundary step ----------------
// s_j = A64 @ s_{j-1} + local_chunk_end;  s stored in g_Q0 columns (b*NCH + j)
__global__ __launch_bounds__(64) void boundary_step(const float* __restrict__ outbuf, int j) {
    __shared__ float s_sm[D];
    const int et = blockIdx.x;   // 8 e-tiles of 64
    const int b  = blockIdx.y;   // 8 batches
    const int tid = threadIdx.x; // 64

    const float* scol = g_Q0 + ((size_t)b * NCH + (j - 1)) * D;
    for (int d = tid * 4; d < D; d += 64 * 4) {
        *(float4*)&s_sm[d] = *(const float4*)&scol[d];
    }
    __syncthreads();

    const int e = et * 64 + tid;
    const float* arow = g_P1 + (size_t)e * D;   // A^64
    float accv = 0.f;
#pragma unroll 4
    for (int d = 0; d < D; d += 4) {
        float4 a = *(const float4*)&arow[d];
        accv += a.x * s_sm[d] + a.y * s_sm[d + 1] + a.z * s_sm[d + 2] + a.w * s_sm[d + 3];
    }
    float v = outbuf[((size_t)b * Tt + (size_t)j * CH - 1) * D + e];
    g_Q0[((size_t)b * NCH + j) * D + e] = accv + v;
}

// ---------------- launcher ----------------
extern "C" void kernel_launch(void* const* d_in, const int* in_sizes, int n_in,
                              void* d_out, int out_size) {
    (void)in_sizes; (void)n_in; (void)out_size;
    const float* x  = (const float*)d_in[0];   // [8, 4096, 512]
    const float* h0 = (const float*)d_in[1];   // [8, 512]
    const float* A  = (const float*)d_in[2];   // [512, 512]
    const float* Bm = (const float*)d_in[3];   // [512, 512]
    float* out = (float*)d_out;                // [8, 4096, 512]

    // K1: out = Bx
    bx_gemm<<<dim3(8, (BS * Tt) / 64), 256>>>(x, Bm, out);

    // K2: A^64 via repeated squaring.  A->P0(A^2)->P1(A^4)->P0->P1->P0->P1(A^64)
    matmul_sq<<<dim3(8, 8), 256>>>(A, 0, 1);
    matmul_sq<<<dim3(8, 8), 256>>>(A, 1, 2);
    matmul_sq<<<dim3(8, 8), 256>>>(A, 2, 1);
    matmul_sq<<<dim3(8, 8), 256>>>(A, 1, 2);
    matmul_sq<<<dim3(8, 8), 256>>>(A, 2, 1);
    matmul_sq<<<dim3(8, 8), 256>>>(A, 1, 2);   // g_P1 = A^64

    // K3: local scans (i = 0 is identity: l_0 = u_0 already in place)
    for (int i = 1; i < CH; i++)
        scan_step<<<dim3(16, 8), 256>>>(A, out, i, 0, 0, 0);

    // K4: boundary carry scan
    init_carry<<<8, D>>>(h0);
    for (int j = 1; j < NCH; j++)
        boundary_step<<<dim3(8, 8), 64>>>(out, j);

    // K5: fixup  P <- A @ P (P starts as carries in g_Q0), out[t] += P
    for (int i = 0; i < CH; i++) {
        int src = (i & 1) ? 4 : 3;   // 3 = g_Q0, 4 = g_Q1
        int dst = (i & 1) ? 3 : 4;
        scan_step<<<dim3(16, 8), 256>>>(A, out, i, 1, src, dst);
    }
}